// round 4
// baseline (speedup 1.0000x reference)
#include <cuda_runtime.h>
#include <math.h>

#define Bx   32
#define Sx   256
#define EMBD 300
#define HIDD 300
#define NTAG 9
#define GATES 1200          // 4*HIDD

// ---------------- scratch (static device globals; no allocs) ----------------
__device__ float g_E [Bx*Sx*EMBD];            // (S,B,300) gathered embeddings
__device__ float g_H [4915200];               // (S,B,600) hidden states (fwd|bwd)
__device__ float g_sc[Bx*Sx];                 // CRF numerator terms
__device__ int   g_ctr[8];                    // recurrence sync counters

__device__ __forceinline__ float fsigm(float x){ return 1.f/(1.f+__expf(-x)); }
__device__ __forceinline__ float ftanh(float x){
    float ax=fabsf(x);
    float t=__expf(-2.f*ax);
    float r=(1.f-t)/(1.f+t);
    return copysignf(r,x);
}

// ---------------- K0: embedding gather + counter reset ----------------
__global__ void k_embed(const int* __restrict__ x, const float* __restrict__ emb){
    if (blockIdx.x==0 && threadIdx.x<8) g_ctr[threadIdx.x]=0;
    int idx = blockIdx.x*blockDim.x + threadIdx.x;
    if (idx < Bx*Sx*EMBD){
        int r = idx/EMBD, k = idx - r*EMBD;
        int s = r/Bx, b = r - s*Bx;
        int tok = __ldg(&x[b*Sx + s]);
        g_E[idx] = __ldg(&emb[(size_t)tok*EMBD + k]);
    }
}

// ---------------- K1: persistent fused BiLSTM (input GEMM + recurrence) ------
#define HS 15          // hidden units per block
#define NHS 20         // hidden slices (20*15=300)
#define NBS 3          // batch slices (11,11,10)
#define NG 60          // 4*HS gate rows per block
#define BMAX 12        // padded per-block batch
#define KSPLIT 5       // k-dim split (5*60=300)
#define RECUR_SMEM ((NG*300*2 + BMAX*300*2 + KSPLIT*NG*BMAX + NG*BMAX + HS*BMAX + NG)*4)

__device__ __forceinline__ void fma4(float& a, float4 w, float4 h){
    a=fmaf(w.x,h.x,a); a=fmaf(w.y,h.y,a); a=fmaf(w.z,h.z,a); a=fmaf(w.w,h.w,a);
}

__device__ __forceinline__ int ld_acquire(const int* p){
    int v;
    asm volatile("ld.acquire.gpu.global.s32 %0, [%1];" : "=r"(v) : "l"(p) : "memory");
    return v;
}
__device__ __forceinline__ void red_release(int* p){
    asm volatile("red.release.gpu.global.add.s32 [%0], %1;" :: "l"(p), "r"(1) : "memory");
}

// 4x4 register-tile partial GEMM over one K-chunk of 60:
// out rows = 4 gate rows (gt*4..), cols = 4 batch (bt*4..), operands in smem.
__device__ __forceinline__ void partial_gemm(
        const float* __restrict__ Wsm, const float* __restrict__ Xsm,
        float* __restrict__ Part, int kp, int gt, int bt){
    float acc[4][4];
    #pragma unroll
    for (int i=0;i<4;i++)
        #pragma unroll
        for (int j=0;j<4;j++) acc[i][j]=0.f;
    const float* wr = Wsm + (gt*4)*300 + kp*60;
    const float* hr = Xsm + (bt*4)*300 + kp*60;
    #pragma unroll
    for (int c=0;c<15;c++){
        int k=c*4;
        float4 w0=*(const float4*)(wr      +k);
        float4 w1=*(const float4*)(wr+300  +k);
        float4 w2=*(const float4*)(wr+600  +k);
        float4 w3=*(const float4*)(wr+900  +k);
        float4 h0=*(const float4*)(hr      +k);
        float4 h1=*(const float4*)(hr+300  +k);
        float4 h2=*(const float4*)(hr+600  +k);
        float4 h3=*(const float4*)(hr+900  +k);
        fma4(acc[0][0],w0,h0); fma4(acc[0][1],w0,h1); fma4(acc[0][2],w0,h2); fma4(acc[0][3],w0,h3);
        fma4(acc[1][0],w1,h0); fma4(acc[1][1],w1,h1); fma4(acc[1][2],w1,h2); fma4(acc[1][3],w1,h3);
        fma4(acc[2][0],w2,h0); fma4(acc[2][1],w2,h1); fma4(acc[2][2],w2,h2); fma4(acc[2][3],w2,h3);
        fma4(acc[3][0],w3,h0); fma4(acc[3][1],w3,h1); fma4(acc[3][2],w3,h2); fma4(acc[3][3],w3,h3);
    }
    #pragma unroll
    for (int i=0;i<4;i++)
        #pragma unroll
        for (int j=0;j<4;j++)
            Part[(kp*NG + gt*4+i)*BMAX + bt*4+j]=acc[i][j];
}

__global__ void __launch_bounds__(256,1) k_recur(
        const float* __restrict__ whhf, const float* __restrict__ whhb,
        const float* __restrict__ wihf, const float* __restrict__ wihb,
        const float* __restrict__ bihf, const float* __restrict__ bhhf,
        const float* __restrict__ bihb, const float* __restrict__ bhhb){
    extern __shared__ float smdyn[];
    float* Wh   = smdyn;                       // [NG][300]  recurrent weights
    float* Wi   = Wh   + NG*300;               // [NG][300]  input weights
    float* Hs   = Wi   + NG*300;               // [BMAX][300] prev hidden (full)
    float* Es   = Hs   + BMAX*300;             // [BMAX][300] embeddings this step
    float* Part = Es   + BMAX*300;             // [KSPLIT][NG][BMAX]
    float* Gx   = Part + KSPLIT*NG*BMAX;       // [NG][BMAX] gx + bias
    float* Cs   = Gx   + NG*BMAX;              // [HS][BMAX] cell state
    float* Bs   = Cs   + HS*BMAX;              // [NG] bias sums

    int bx  = blockIdx.x;
    int dir = bx / (NHS*NBS);
    int r   = bx % (NHS*NBS);
    int hs  = r / NBS;
    int bs  = r % NBS;
    int bch = (bs<2)?11:10;
    int b0g = bs*11;
    int j0  = hs*HS;
    const float* whh = dir ? whhb : whhf;
    const float* wih = dir ? wihb : wihf;
    const float* bih = dir ? bihb : bihf;
    const float* bhh = dir ? bhhb : bhhf;
    int t = threadIdx.x;

    for (int i=t;i<NG*300;i+=256){
        int row=i/300, k=i-row*300;
        int type=row/HS, jj=row-type*HS;
        int grow = type*HIDD + j0 + jj;
        Wh[i]=whh[(size_t)grow*HIDD + k];
        Wi[i]=wih[(size_t)grow*EMBD + k];
    }
    if (t<NG){
        int type=t/HS, jj=t-type*HS;
        int grow = type*HIDD + j0 + jj;
        Bs[t]=bih[grow]+bhh[grow];
    }
    for (int i=t;i<BMAX*300;i+=256) Hs[i]=0.f;
    for (int i=t;i<HS*BMAX;i+=256)  Cs[i]=0.f;
    __syncthreads();

    bool comp=(t<225);
    int kp=0, gt=0, bt=0;
    if (comp){ kp=t/45; int rem=t%45; gt=rem/3; bt=rem%3; }
    int* ctr = g_ctr + dir*NBS + bs;
    bool mycell = (t < HS*bch);
    int cb = t/HS, cj = t - cb*HS;

    for (int step=0; step<Sx; step++){
        int s = dir ? (Sx-1-step) : step;

        // ---- load Es(s): rows (s*Bx+b0g .. +bch) are contiguous in g_E
        {
            const float4* src = (const float4*)(g_E + (size_t)(s*Bx + b0g)*EMBD);
            int n4 = bch*75;
            for (int i=t;i<n4;i+=256) ((float4*)Es)[i] = src[i];
        }
        __syncthreads();                                   // A

        // ---- gx partials (independent of peers' h -> fills spin slack)
        if (comp) partial_gemm(Wi, Es, Part, kp, gt, bt);
        __syncthreads();                                   // B

        // ---- reduce gx partials + bias into Gx
        for (int i=t;i<NG*BMAX;i+=256){
            int row=i/BMAX;
            float v=Bs[row];
            #pragma unroll
            for (int kq=0;kq<KSPLIT;kq++) v += Part[kq*NG*BMAX + i];
            Gx[i]=v;
        }

        // ---- wait for peers' h(s-1), then load full h into Hs
        if (step>0){
            int sprev = dir ? s+1 : s-1;
            int target = NHS*step;
            while (ld_acquire(ctr) < target) { }
            const float4* hbase = (const float4*)(g_H + (size_t)sprev*Bx*(2*HIDD) + dir*HIDD);
            int n4 = bch*75;
            for (int i=t;i<n4;i+=256){
                int b=i/75, q=i-b*75;
                ((float4*)Hs)[b*75+q] = hbase[(size_t)(b0g+b)*150 + q];
            }
        }
        __syncthreads();                                   // C

        // ---- recurrent partials
        if (comp) partial_gemm(Wh, Hs, Part, kp, gt, bt);
        __syncthreads();                                   // D0

        // ---- cell update
        if (mycell){
            float gi=Gx[(0*HS+cj)*BMAX+cb];
            float gf=Gx[(1*HS+cj)*BMAX+cb];
            float gg=Gx[(2*HS+cj)*BMAX+cb];
            float go=Gx[(3*HS+cj)*BMAX+cb];
            #pragma unroll
            for (int kq=0;kq<KSPLIT;kq++){
                gi += Part[(kq*NG + 0*HS+cj)*BMAX + cb];
                gf += Part[(kq*NG + 1*HS+cj)*BMAX + cb];
                gg += Part[(kq*NG + 2*HS+cj)*BMAX + cb];
                go += Part[(kq*NG + 3*HS+cj)*BMAX + cb];
            }
            float co=Cs[cj*BMAX+cb];
            float cn=fsigm(gf)*co + fsigm(gi)*ftanh(gg);
            float hn=fsigm(go)*ftanh(cn);
            Cs[cj*BMAX+cb]=cn;
            g_H[((size_t)(s*Bx + b0g + cb))*(2*HIDD) + dir*HIDD + j0 + cj]=hn;
        }
        __syncthreads();                                   // D
        if (t==0) red_release(ctr);
    }
}

// ---------------- K3a: logits + softmax + CRF numerator terms ----------------
__global__ void __launch_bounds__(288) k_head(
        const float* __restrict__ linw, const float* __restrict__ linb,
        const int* __restrict__ y, const float* __restrict__ start_t,
        const float* __restrict__ end_t, const float* __restrict__ trans,
        float* __restrict__ out){
    __shared__ float sh[2*HIDD];
    __shared__ float lg[NTAG];
    int bxid=blockIdx.x;
    int b=bxid/Sx, s=bxid%Sx;
    int t=threadIdx.x;
    const float* hrow=g_H + (size_t)(s*Bx+b)*(2*HIDD);
    for (int k=t;k<2*HIDD;k+=288) sh[k]=hrow[k];
    __syncthreads();
    int w=t>>5, lane=t&31;
    float acc=0.f;
    for (int k=lane;k<2*HIDD;k+=32) acc=fmaf(sh[k],__ldg(&linw[w*(2*HIDD)+k]),acc);
    #pragma unroll
    for (int off=16;off;off>>=1) acc += __shfl_down_sync(0xffffffffu,acc,off);
    if (lane==0) lg[w]=acc+__ldg(&linb[w]);
    __syncthreads();
    if (t==0){
        float m=lg[0];
        #pragma unroll
        for (int i=1;i<NTAG;i++) m=fmaxf(m,lg[i]);
        float e[NTAG]; float ssum=0.f;
        #pragma unroll
        for (int i=0;i<NTAG;i++){ e[i]=expf(lg[i]-m); ssum+=e[i]; }
        float inv=1.f/ssum;
        float* po=out + ((size_t)b*Sx + s)*NTAG;
        float pr[NTAG];
        #pragma unroll
        for (int i=0;i<NTAG;i++){ pr[i]=e[i]*inv; po[i]=pr[i]; }
        int yc=__ldg(&y[b*Sx+s]);
        float term=pr[yc];
        if (s==0) term += __ldg(&start_t[yc]);
        else      term += __ldg(&trans[__ldg(&y[b*Sx+s-1])*NTAG + yc]);
        if (s==Sx-1) term += __ldg(&end_t[yc]);
        g_sc[b*Sx+s]=term;
    }
}

// ---------------- K3b: CRF forward algorithm + loss ----------------
__global__ void __launch_bounds__(288) k_crf(
        const float* __restrict__ start_t, const float* __restrict__ end_t,
        const float* __restrict__ trans, float* __restrict__ out){
    __shared__ float alpha[Bx][NTAG];
    __shared__ float str[NTAG*NTAG];
    __shared__ float sst[NTAG], sen[NTAG];
    __shared__ float res[Bx];
    const float* probs = out;   // written by k_head
    int t=threadIdx.x;
    if (t<NTAG*NTAG) str[t]=trans[t];
    if (t<NTAG){ sst[t]=start_t[t]; sen[t]=end_t[t]; }
    int b=t/NTAG, j=t-b*NTAG;
    __syncthreads();
    alpha[b][j]=sst[j]+probs[((size_t)b*Sx+0)*NTAG+j];
    __syncthreads();
    float em_next=probs[((size_t)b*Sx+1)*NTAG+j];
    for (int s=1;s<Sx;s++){
        float em=em_next;
        if (s<Sx-1) em_next=probs[((size_t)b*Sx+s+1)*NTAG+j];
        float m=-1e30f; float v[NTAG];
        #pragma unroll
        for (int i=0;i<NTAG;i++){ v[i]=alpha[b][i]+str[i*NTAG+j]; m=fmaxf(m,v[i]); }
        float ssum=0.f;
        #pragma unroll
        for (int i=0;i<NTAG;i++) ssum+=expf(v[i]-m);
        float nxt=m+logf(ssum)+em;
        __syncthreads();
        alpha[b][j]=nxt;
        __syncthreads();
    }
    if (t<Bx){
        int bb=t;
        float m=-1e30f;
        #pragma unroll
        for (int i=0;i<NTAG;i++) m=fmaxf(m,alpha[bb][i]+sen[i]);
        float ssum=0.f;
        #pragma unroll
        for (int i=0;i<NTAG;i++) ssum+=expf(alpha[bb][i]+sen[i]-m);
        float denom=m+logf(ssum);
        float sc=0.f;
        for (int s=0;s<Sx;s++) sc+=g_sc[bb*Sx+s];
        res[bb]=sc-denom;
    }
    __syncthreads();
    if (t==0){
        float llh=0.f;
        #pragma unroll
        for (int bb=0;bb<Bx;bb++) llh+=res[bb];
        out[(size_t)Bx*Sx*NTAG]=-llh;
    }
}

// ---------------- launcher ----------------
extern "C" void kernel_launch(void* const* d_in, const int* in_sizes, int n_in,
                              void* d_out, int out_size){
    const int*   x     =(const int*)  d_in[0];
    const int*   y     =(const int*)  d_in[1];
    const float* emb   =(const float*)d_in[2];
    const float* wihf  =(const float*)d_in[3];
    const float* whhf  =(const float*)d_in[4];
    const float* bihf  =(const float*)d_in[5];
    const float* bhhf  =(const float*)d_in[6];
    const float* wihb  =(const float*)d_in[7];
    const float* whhb  =(const float*)d_in[8];
    const float* bihb  =(const float*)d_in[9];
    const float* bhhb  =(const float*)d_in[10];
    const float* linw  =(const float*)d_in[11];
    const float* linb  =(const float*)d_in[12];
    const float* startt=(const float*)d_in[13];
    const float* endt  =(const float*)d_in[14];
    const float* trans =(const float*)d_in[15];
    float* out=(float*)d_out;
    (void)in_sizes; (void)n_in; (void)out_size;

    static int smem_set = 0;
    if (!smem_set){
        cudaFuncSetAttribute(k_recur, cudaFuncAttributeMaxDynamicSharedMemorySize, RECUR_SMEM);
        smem_set = 1;
    }

    k_embed<<<(Bx*Sx*EMBD+255)/256,256>>>(x, emb);
    k_recur<<<2*NHS*NBS,256,RECUR_SMEM>>>(whhf, whhb, wihf, wihb,
                                          bihf, bhhf, bihb, bhhb);
    k_head<<<Bx*Sx,288>>>(linw, linb, y, startt, endt, trans, out);
    k_crf<<<1,288>>>(startt, endt, trans, out);
}

// round 5
// speedup vs baseline: 1.4789x; 1.4789x over previous
#include <cuda_runtime.h>
#include <math.h>

#define Bx   32
#define Sx   256
#define EMBD 300
#define HIDD 300
#define NTAG 9
#define GATES 1200          // 4*HIDD
#define NCOL  2400          // both directions

// ---------------- scratch (static device globals; no allocs) ----------------
__device__ float g_E [Bx*Sx*EMBD];            // (S,B,300) gathered embeddings
__device__ float g_gx[19660800];              // (S,B,2400) input-transform + biases
__device__ float g_H [4915200];               // (S,B,600) hidden states (fwd|bwd)
__device__ float g_sc[Bx*Sx];                 // CRF numerator terms
__device__ int   g_ctr[8];                    // recurrence sync counters

__device__ __forceinline__ float fsigm(float x){ return 1.f/(1.f+__expf(-x)); }
__device__ __forceinline__ float ftanh(float x){
    float ax=fabsf(x);
    float t=__expf(-2.f*ax);
    float r=(1.f-t)/(1.f+t);
    return copysignf(r,x);
}

// ---- packed fp32x2 helpers (sm_103a FFMA2 path) ----
__device__ __forceinline__ unsigned long long pk2(float lo, float hi){
    unsigned long long r;
    asm("mov.b64 %0, {%1,%2};" : "=l"(r) : "f"(lo), "f"(hi));
    return r;
}
__device__ __forceinline__ void ffma2(unsigned long long& d,
                                      unsigned long long a, unsigned long long b){
    asm("fma.rn.f32x2 %0, %1, %2, %0;" : "+l"(d) : "l"(a), "l"(b));
}
__device__ __forceinline__ void upk2(float& lo, float& hi, unsigned long long v){
    asm("mov.b64 {%0,%1}, %2;" : "=f"(lo), "=f"(hi) : "l"(v));
}

// ---------------- K0: embedding gather + counter reset ----------------
__global__ void k_embed(const int* __restrict__ x, const float* __restrict__ emb){
    if (blockIdx.x==0 && threadIdx.x<8) g_ctr[threadIdx.x]=0;
    int idx = blockIdx.x*blockDim.x + threadIdx.x;
    if (idx < Bx*Sx*EMBD){
        int r = idx/EMBD, k = idx - r*EMBD;
        int s = r/Bx, b = r - s*Bx;
        int tok = __ldg(&x[b*Sx + s]);
        g_E[idx] = __ldg(&emb[(size_t)tok*EMBD + k]);
    }
}

// ---------------- K1: gx GEMM (8192 x 2400 x 300), fp32x2 tiled ----------------
__global__ void __launch_bounds__(256) k_gx(
        const float* __restrict__ wf, const float* __restrict__ wb,
        const float* __restrict__ bif, const float* __restrict__ bhf,
        const float* __restrict__ bib, const float* __restrict__ bhb){
    __shared__ float As[8][132];
    __shared__ float Bs[8][128];
    int t  = threadIdx.x;
    int m0 = blockIdx.x*128;
    int n0 = blockIdx.y*128;
    int tx = t & 15, ty = t >> 4;

    unsigned long long acc2[8][4];
    #pragma unroll
    for (int i=0;i<8;i++)
        #pragma unroll
        for (int j=0;j<4;j++) acc2[i][j]=pk2(0.f,0.f);

    int arow = t>>1, ahalf = t&1;
    int bn = t>>1,  bh = t&1;
    bool brow_ok = (n0+bn) < NCOL;
    const float* wrp = brow_ok
        ? ((n0+bn) < GATES ? wf + (size_t)(n0+bn)*EMBD
                           : wb + (size_t)(n0+bn-GATES)*EMBD)
        : wf;

    float4 aR, bRv;
    {
        aR  = *(const float4*)(g_E + (size_t)(m0+arow)*EMBD + ahalf*4);
        bRv = brow_ok ? *(const float4*)(wrp + bh*4)
                      : make_float4(0.f,0.f,0.f,0.f);
    }
    for (int ck=0; ck<38; ck++){
        __syncthreads();
        {   float av[4]={aR.x,aR.y,aR.z,aR.w};
            float bv[4]={bRv.x,bRv.y,bRv.z,bRv.w};
            #pragma unroll
            for (int i=0;i<4;i++){ As[ahalf*4+i][arow]=av[i]; Bs[bh*4+i][bn]=bv[i]; }
        }
        __syncthreads();
        if (ck < 37){
            int k0=(ck+1)*8;
            int ka = k0 + ahalf*4;
            int kb = k0 + bh*4;
            aR = (ka<EMBD) ? *(const float4*)(g_E + (size_t)(m0+arow)*EMBD + ka)
                           : make_float4(0.f,0.f,0.f,0.f);
            bRv = (brow_ok && kb<EMBD) ? *(const float4*)(wrp + kb)
                                       : make_float4(0.f,0.f,0.f,0.f);
        }
        #pragma unroll
        for (int kk=0;kk<8;kk++){
            float4 a0=*(const float4*)&As[kk][ty*8];
            float4 a1=*(const float4*)&As[kk][ty*8+4];
            float av[8]={a0.x,a0.y,a0.z,a0.w,a1.x,a1.y,a1.z,a1.w};
            unsigned long long ad[8];
            #pragma unroll
            for (int i=0;i<8;i++) ad[i]=pk2(av[i],av[i]);
            ulonglong2 bq0 = *(const ulonglong2*)&Bs[kk][tx*8];
            ulonglong2 bq1 = *(const ulonglong2*)&Bs[kk][tx*8+4];
            unsigned long long bp[4]={bq0.x,bq0.y,bq1.x,bq1.y};
            #pragma unroll
            for (int i=0;i<8;i++)
                #pragma unroll
                for (int j=0;j<4;j++)
                    ffma2(acc2[i][j], ad[i], bp[j]);
        }
    }
    #pragma unroll
    for (int i=0;i<8;i++){
        int gm = m0 + ty*8 + i;
        float vv[8];
        #pragma unroll
        for (int j=0;j<4;j++) upk2(vv[2*j], vv[2*j+1], acc2[i][j]);
        #pragma unroll
        for (int j0=0;j0<8;j0+=4){
            int gn = n0 + tx*8 + j0;
            if (gn < NCOL){
                float ww[4];
                #pragma unroll
                for (int j=0;j<4;j++){
                    int c=gn+j;
                    float bias = (c<GATES)? bif[c]+bhf[c] : bib[c-GATES]+bhb[c-GATES];
                    ww[j]=vv[j0+j]+bias;
                }
                *(float4*)(g_gx + (size_t)gm*NCOL + gn) =
                    make_float4(ww[0],ww[1],ww[2],ww[3]);
            }
        }
    }
}

// ---------------- K2: persistent bidirectional LSTM recurrence ----------------
#define HS 15          // hidden units per block
#define NHS 20         // hidden slices (20*15=300)
#define NBS 3          // batch slices (11,11,10)
#define NG 60          // 4*HS gate rows per block
#define BMAX 12        // padded per-block batch (6 pairs)
#define KSPLIT 15      // k-dim split (15*20=300)
#define PROW 13        // padded Part row stride (in floats)
#define HP   302       // padded Hs2 pair stride (in float2)
// smem floats: WhT[300][60] + Hs2[6][HP]f2 + Part[15][60][PROW] + Cs[HS][BMAX]
#define RECUR_SMEM ((300*60 + 6*HP*2 + KSPLIT*NG*PROW + HS*BMAX)*4)

__device__ __forceinline__ int ld_acquire(const int* p){
    int v;
    asm volatile("ld.acquire.gpu.global.s32 %0, [%1];" : "=r"(v) : "l"(p) : "memory");
    return v;
}
__device__ __forceinline__ void red_release(int* p){
    asm volatile("red.release.gpu.global.add.s32 [%0], %1;" :: "l"(p), "r"(1) : "memory");
}

__global__ void __launch_bounds__(256,1) k_recur(
        const float* __restrict__ whhf, const float* __restrict__ whhb){
    extern __shared__ float smdyn[];
    float* WhT  = smdyn;                        // [300][60] transposed (k-major)
    float* Hs2f = WhT  + 300*60;                // [6][HP] float2 pair-major (as floats)
    float* Part = Hs2f + 6*HP*2;                // [15][60][PROW]
    float* Cs   = Part + KSPLIT*NG*PROW;        // [HS][BMAX]

    int bx  = blockIdx.x;
    int dir = bx / (NHS*NBS);
    int r   = bx % (NHS*NBS);
    int hs  = r / NBS;
    int bs  = r % NBS;
    int bch = (bs<2)?11:10;
    int b0g = bs*11;
    int j0  = hs*HS;
    const float* whh = dir ? whhb : whhf;
    int t = threadIdx.x;

    // load W_hh slice transposed: WhT[k][row], row = type*HS+jj -> gate row type*HIDD+j0+jj
    for (int i=t;i<NG*300;i+=256){
        int row=i/300, k=i-row*300;
        int type=row/HS, jj=row-type*HS;
        WhT[k*60+row]=whh[(size_t)(type*HIDD + j0 + jj)*HIDD + k];
    }
    for (int i=t;i<6*HP*2;i+=256) Hs2f[i]=0.f;
    for (int i=t;i<HS*BMAX;i+=256) Cs[i]=0.f;
    __syncthreads();

    // gemm mapping: half-warp groups share kp (h broadcast), gt varies
    bool comp = (t<240) && ((t&15)<15);
    int kp = t>>4;       // 0..14
    int gt = t&15;       // 0..14 (active)
    int* ctr = g_ctr + dir*NBS + bs;
    bool mycell = (t < HS*bch);
    int cb = t/HS, cj = t - cb*HS;

    for (int step=0; step<Sx; step++){
        int s = dir ? (Sx-1-step) : step;

        // prefetch gx (independent of h; hides DRAM latency under spin)
        float pgi=0.f,pgf=0.f,pgg=0.f,pgo=0.f;
        if (mycell){
            const float* gp = g_gx + ((size_t)(s*Bx + b0g + cb))*NCOL + dir*GATES + (j0+cj);
            pgi=gp[0]; pgf=gp[HIDD]; pgg=gp[2*HIDD]; pgo=gp[3*HIDD];
        }

        if (step>0){
            int sprev = dir ? s+1 : s-1;
            int target = NHS*step;
            while (ld_acquire(ctr) < target) { }
            // load h(s-1) and transpose into pair-major Hs2: Hs2[b/2][k].{x,y}
            const float* hbase = g_H + (size_t)sprev*Bx*(2*HIDD) + dir*HIDD;
            int n = bch*300;
            for (int i=t;i<n;i+=256){
                int b=i/300, k=i-b*300;
                Hs2f[(b>>1)*(HP*2) + k*2 + (b&1)] = hbase[(size_t)(b0g+b)*(2*HIDD) + k];
            }
        }
        __syncthreads();                                   // A

        // ---- packed-fp32 recurrent GEMM: 4 rows x 6 pairs x 20 k per thread
        if (comp){
            unsigned long long acc[4][6];
            #pragma unroll
            for (int i=0;i<4;i++)
                #pragma unroll
                for (int p=0;p<6;p++) acc[i][p]=pk2(0.f,0.f);
            const float* wt = WhT + (kp*20)*60 + gt*4;
            const float* hb = Hs2f + kp*40;
            #pragma unroll
            for (int c=0;c<5;c++){
                int k=c*4;
                float4 wk0=*(const float4*)(wt + (k+0)*60);
                float4 wk1=*(const float4*)(wt + (k+1)*60);
                float4 wk2=*(const float4*)(wt + (k+2)*60);
                float4 wk3=*(const float4*)(wt + (k+3)*60);
                unsigned long long wd[4][4];
                wd[0][0]=pk2(wk0.x,wk0.x); wd[1][0]=pk2(wk0.y,wk0.y);
                wd[2][0]=pk2(wk0.z,wk0.z); wd[3][0]=pk2(wk0.w,wk0.w);
                wd[0][1]=pk2(wk1.x,wk1.x); wd[1][1]=pk2(wk1.y,wk1.y);
                wd[2][1]=pk2(wk1.z,wk1.z); wd[3][1]=pk2(wk1.w,wk1.w);
                wd[0][2]=pk2(wk2.x,wk2.x); wd[1][2]=pk2(wk2.y,wk2.y);
                wd[2][2]=pk2(wk2.z,wk2.z); wd[3][2]=pk2(wk2.w,wk2.w);
                wd[0][3]=pk2(wk3.x,wk3.x); wd[1][3]=pk2(wk3.y,wk3.y);
                wd[2][3]=pk2(wk3.z,wk3.z); wd[3][3]=pk2(wk3.w,wk3.w);
                #pragma unroll
                for (int p=0;p<6;p++){
                    const float* ha = hb + p*(HP*2) + k*2;
                    ulonglong2 h01 = *(const ulonglong2*)(ha);
                    ulonglong2 h23 = *(const ulonglong2*)(ha+4);
                    #pragma unroll
                    for (int rr=0;rr<4;rr++){
                        ffma2(acc[rr][p], wd[rr][0], h01.x);
                        ffma2(acc[rr][p], wd[rr][1], h01.y);
                        ffma2(acc[rr][p], wd[rr][2], h23.x);
                        ffma2(acc[rr][p], wd[rr][3], h23.y);
                    }
                }
            }
            #pragma unroll
            for (int rr=0;rr<4;rr++){
                int row = gt*4+rr;
                #pragma unroll
                for (int p=0;p<6;p++){
                    float lo,hi; upk2(lo,hi,acc[rr][p]);
                    Part[(kp*NG+row)*PROW + 2*p  ]=lo;
                    Part[(kp*NG+row)*PROW + 2*p+1]=hi;
                }
            }
        }
        __syncthreads();                                   // B

        // ---- cell update
        if (mycell){
            float gi=pgi, gf=pgf, gg=pgg, go=pgo;
            #pragma unroll
            for (int kq=0;kq<KSPLIT;kq++){
                gi += Part[(kq*NG + 0*HS+cj)*PROW + cb];
                gf += Part[(kq*NG + 1*HS+cj)*PROW + cb];
                gg += Part[(kq*NG + 2*HS+cj)*PROW + cb];
                go += Part[(kq*NG + 3*HS+cj)*PROW + cb];
            }
            float co=Cs[cj*BMAX+cb];
            float cn=fsigm(gf)*co + fsigm(gi)*ftanh(gg);
            float hn=fsigm(go)*ftanh(cn);
            Cs[cj*BMAX+cb]=cn;
            g_H[((size_t)(s*Bx + b0g + cb))*(2*HIDD) + dir*HIDD + j0 + cj]=hn;
        }
        __syncthreads();                                   // C
        if (t==0) red_release(ctr);
    }
}

// ---------------- K3a: logits + softmax + CRF numerator terms ----------------
__global__ void __launch_bounds__(288) k_head(
        const float* __restrict__ linw, const float* __restrict__ linb,
        const int* __restrict__ y, const float* __restrict__ start_t,
        const float* __restrict__ end_t, const float* __restrict__ trans,
        float* __restrict__ out){
    __shared__ float sh[2*HIDD];
    __shared__ float lg[NTAG];
    int bxid=blockIdx.x;
    int b=bxid/Sx, s=bxid%Sx;
    int t=threadIdx.x;
    const float* hrow=g_H + (size_t)(s*Bx+b)*(2*HIDD);
    for (int k=t;k<2*HIDD;k+=288) sh[k]=hrow[k];
    __syncthreads();
    int w=t>>5, lane=t&31;
    float acc=0.f;
    for (int k=lane;k<2*HIDD;k+=32) acc=fmaf(sh[k],__ldg(&linw[w*(2*HIDD)+k]),acc);
    #pragma unroll
    for (int off=16;off;off>>=1) acc += __shfl_down_sync(0xffffffffu,acc,off);
    if (lane==0) lg[w]=acc+__ldg(&linb[w]);
    __syncthreads();
    if (t==0){
        float m=lg[0];
        #pragma unroll
        for (int i=1;i<NTAG;i++) m=fmaxf(m,lg[i]);
        float e[NTAG]; float ssum=0.f;
        #pragma unroll
        for (int i=0;i<NTAG;i++){ e[i]=expf(lg[i]-m); ssum+=e[i]; }
        float inv=1.f/ssum;
        float* po=out + ((size_t)b*Sx + s)*NTAG;
        float pr[NTAG];
        #pragma unroll
        for (int i=0;i<NTAG;i++){ pr[i]=e[i]*inv; po[i]=pr[i]; }
        int yc=__ldg(&y[b*Sx+s]);
        float term=pr[yc];
        if (s==0) term += __ldg(&start_t[yc]);
        else      term += __ldg(&trans[__ldg(&y[b*Sx+s-1])*NTAG + yc]);
        if (s==Sx-1) term += __ldg(&end_t[yc]);
        g_sc[b*Sx+s]=term;
    }
}

// ---------------- K3b: CRF forward, warp-per-batch (no block syncs in loop) ----
__global__ void __launch_bounds__(1024) k_crf(
        const float* __restrict__ start_t, const float* __restrict__ end_t,
        const float* __restrict__ trans, float* __restrict__ out){
    __shared__ float res[Bx];
    const float* probs = out;    // written by k_head
    int t=threadIdx.x;
    int w=t>>5, lane=t&31;       // warp w = batch w
    int j = (lane<NTAG)? lane : 0;

    float tcol[NTAG];
    #pragma unroll
    for (int i=0;i<NTAG;i++) tcol[i]=__ldg(&trans[i*NTAG+j]);

    float alpha = __ldg(&start_t[j]) + probs[((size_t)w*Sx+0)*NTAG+j];
    float em_next = probs[((size_t)w*Sx+1)*NTAG+j];
    for (int s=1;s<Sx;s++){
        float em = em_next;
        if (s<Sx-1) em_next = probs[((size_t)w*Sx+s+1)*NTAG+j];
        float a[NTAG];
        #pragma unroll
        for (int i=0;i<NTAG;i++) a[i]=__shfl_sync(0xffffffffu, alpha, i);
        float m=-1e30f;
        #pragma unroll
        for (int i=0;i<NTAG;i++){ a[i]+=tcol[i]; m=fmaxf(m,a[i]); }
        float ssum=0.f;
        #pragma unroll
        for (int i=0;i<NTAG;i++) ssum+=__expf(a[i]-m);
        alpha = m + __logf(ssum) + em;
    }
    // denom = logsumexp(alpha + end_t)
    float v = alpha + __ldg(&end_t[j]);
    float vm=-1e30f;
    #pragma unroll
    for (int i=0;i<NTAG;i++) vm=fmaxf(vm,__shfl_sync(0xffffffffu,v,i));
    float se=0.f;
    #pragma unroll
    for (int i=0;i<NTAG;i++) se+=__expf(__shfl_sync(0xffffffffu,v,i)-vm);
    float denom = vm + __logf(se);
    // score = sum of per-step terms
    float sc=0.f;
    for (int s=lane;s<Sx;s+=32) sc+=g_sc[w*Sx+s];
    #pragma unroll
    for (int off=16;off;off>>=1) sc += __shfl_down_sync(0xffffffffu,sc,off);
    if (lane==0) res[w]=sc-denom;
    __syncthreads();
    if (t==0){
        float llh=0.f;
        #pragma unroll
        for (int bb=0;bb<Bx;bb++) llh+=res[bb];
        out[(size_t)Bx*Sx*NTAG]=-llh;
    }
}

// ---------------- launcher ----------------
extern "C" void kernel_launch(void* const* d_in, const int* in_sizes, int n_in,
                              void* d_out, int out_size){
    const int*   x     =(const int*)  d_in[0];
    const int*   y     =(const int*)  d_in[1];
    const float* emb   =(const float*)d_in[2];
    const float* wihf  =(const float*)d_in[3];
    const float* whhf  =(const float*)d_in[4];
    const float* bihf  =(const float*)d_in[5];
    const float* bhhf  =(const float*)d_in[6];
    const float* wihb  =(const float*)d_in[7];
    const float* whhb  =(const float*)d_in[8];
    const float* bihb  =(const float*)d_in[9];
    const float* bhhb  =(const float*)d_in[10];
    const float* linw  =(const float*)d_in[11];
    const float* linb  =(const float*)d_in[12];
    const float* startt=(const float*)d_in[13];
    const float* endt  =(const float*)d_in[14];
    const float* trans =(const float*)d_in[15];
    float* out=(float*)d_out;
    (void)in_sizes; (void)n_in; (void)out_size;

    static int smem_set = 0;
    if (!smem_set){
        cudaFuncSetAttribute(k_recur, cudaFuncAttributeMaxDynamicSharedMemorySize, RECUR_SMEM);
        smem_set = 1;
    }

    k_embed<<<(Bx*Sx*EMBD+255)/256,256>>>(x, emb);
    dim3 gg(8192/128, (NCOL+127)/128);
    k_gx<<<gg,256>>>(wihf, wihb, bihf, bhhf, bihb, bhhb);
    k_recur<<<2*NHS*NBS,256,RECUR_SMEM>>>(whhf, whhb);
    k_head<<<Bx*Sx,288>>>(linw, linb, y, startt, endt, trans, out);
    k_crf<<<1,1024>>>(startt, endt, trans, out);
}

// round 6
// speedup vs baseline: 1.6534x; 1.1180x over previous
#include <cuda_runtime.h>
#include <math.h>

#define Bx   32
#define Sx   256
#define EMBD 300
#define HIDD 300
#define NTAG 9
#define GATES 1200          // 4*HIDD
#define NCOL  2400          // both directions

// ---------------- scratch (static device globals; no allocs) ----------------
__device__ float g_gx[19660800];              // (S,B,2400) input-transform + biases
__device__ float g_H [4915200];               // (S,B,600) hidden states (fwd|bwd)
__device__ float g_sc[Bx*Sx];                 // CRF numerator terms
__device__ int   g_ctr[8];                    // recurrence sync counters

__device__ __forceinline__ float fsigm(float x){ return 1.f/(1.f+__expf(-x)); }
__device__ __forceinline__ float ftanh(float x){
    float ax=fabsf(x);
    float t=__expf(-2.f*ax);
    float r=(1.f-t)/(1.f+t);
    return copysignf(r,x);
}

// ---- packed fp32x2 helpers (sm_103a FFMA2 path) ----
__device__ __forceinline__ unsigned long long pk2(float lo, float hi){
    unsigned long long r;
    asm("mov.b64 %0, {%1,%2};" : "=l"(r) : "f"(lo), "f"(hi));
    return r;
}
__device__ __forceinline__ void ffma2(unsigned long long& d,
                                      unsigned long long a, unsigned long long b){
    asm("fma.rn.f32x2 %0, %1, %2, %0;" : "+l"(d) : "l"(a), "l"(b));
}
__device__ __forceinline__ void upk2(float& lo, float& hi, unsigned long long v){
    asm("mov.b64 {%0,%1}, %2;" : "=f"(lo), "=f"(hi) : "l"(v));
}

// ---------------- K0: counter reset ----------------
__global__ void k_init(){
    if (threadIdx.x<8) g_ctr[threadIdx.x]=0;
}

// ---------------- K1: fused embed + gx GEMM (8192 x 2400 x 300) --------------
__global__ void __launch_bounds__(256) k_gx(
        const int* __restrict__ x, const float* __restrict__ emb,
        const float* __restrict__ wf, const float* __restrict__ wb,
        const float* __restrict__ bif, const float* __restrict__ bhf,
        const float* __restrict__ bib, const float* __restrict__ bhb){
    __shared__ float As[8][132];
    __shared__ float Bs[8][128];
    int t  = threadIdx.x;
    int m0 = blockIdx.x*128;
    int n0 = blockIdx.y*128;
    int tx = t & 15, ty = t >> 4;

    unsigned long long acc2[8][4];
    #pragma unroll
    for (int i=0;i<8;i++)
        #pragma unroll
        for (int j=0;j<4;j++) acc2[i][j]=pk2(0.f,0.f);

    int arow = t>>1, ahalf = t&1;
    int bn = t>>1,  bh = t&1;
    // embedding row for A: m = m0+arow -> (s,b) -> token
    int m_ = m0 + arow;
    int s_ = m_ >> 5, b_ = m_ & 31;
    const float* arowp = emb + (size_t)__ldg(&x[b_*Sx + s_])*EMBD;

    bool brow_ok = (n0+bn) < NCOL;
    const float* wrp = brow_ok
        ? ((n0+bn) < GATES ? wf + (size_t)(n0+bn)*EMBD
                           : wb + (size_t)(n0+bn-GATES)*EMBD)
        : wf;

    float4 aR, bRv;
    {
        aR  = *(const float4*)(arowp + ahalf*4);
        bRv = brow_ok ? *(const float4*)(wrp + bh*4)
                      : make_float4(0.f,0.f,0.f,0.f);
    }
    for (int ck=0; ck<38; ck++){
        __syncthreads();
        {   float av[4]={aR.x,aR.y,aR.z,aR.w};
            float bv[4]={bRv.x,bRv.y,bRv.z,bRv.w};
            #pragma unroll
            for (int i=0;i<4;i++){ As[ahalf*4+i][arow]=av[i]; Bs[bh*4+i][bn]=bv[i]; }
        }
        __syncthreads();
        if (ck < 37){
            int k0=(ck+1)*8;
            int ka = k0 + ahalf*4;
            int kb = k0 + bh*4;
            aR = (ka<EMBD) ? *(const float4*)(arowp + ka)
                           : make_float4(0.f,0.f,0.f,0.f);
            bRv = (brow_ok && kb<EMBD) ? *(const float4*)(wrp + kb)
                                       : make_float4(0.f,0.f,0.f,0.f);
        }
        #pragma unroll
        for (int kk=0;kk<8;kk++){
            float4 a0=*(const float4*)&As[kk][ty*8];
            float4 a1=*(const float4*)&As[kk][ty*8+4];
            float av[8]={a0.x,a0.y,a0.z,a0.w,a1.x,a1.y,a1.z,a1.w};
            unsigned long long ad[8];
            #pragma unroll
            for (int i=0;i<8;i++) ad[i]=pk2(av[i],av[i]);
            ulonglong2 bq0 = *(const ulonglong2*)&Bs[kk][tx*8];
            ulonglong2 bq1 = *(const ulonglong2*)&Bs[kk][tx*8+4];
            unsigned long long bp[4]={bq0.x,bq0.y,bq1.x,bq1.y};
            #pragma unroll
            for (int i=0;i<8;i++)
                #pragma unroll
                for (int j=0;j<4;j++)
                    ffma2(acc2[i][j], ad[i], bp[j]);
        }
    }
    #pragma unroll
    for (int i=0;i<8;i++){
        int gm = m0 + ty*8 + i;
        float vv[8];
        #pragma unroll
        for (int j=0;j<4;j++) upk2(vv[2*j], vv[2*j+1], acc2[i][j]);
        #pragma unroll
        for (int j0=0;j0<8;j0+=4){
            int gn = n0 + tx*8 + j0;
            if (gn < NCOL){
                float ww[4];
                #pragma unroll
                for (int j=0;j<4;j++){
                    int c=gn+j;
                    float bias = (c<GATES)? bif[c]+bhf[c] : bib[c-GATES]+bhb[c-GATES];
                    ww[j]=vv[j0+j]+bias;
                }
                *(float4*)(g_gx + (size_t)gm*NCOL + gn) =
                    make_float4(ww[0],ww[1],ww[2],ww[3]);
            }
        }
    }
}

// ---------------- K2: persistent bidirectional LSTM recurrence ----------------
#define HS 15          // hidden units per block
#define NHS 20         // hidden slices (20*15=300)
#define NBS 3          // batch slices (11,11,10)
#define NG 60          // 4*HS gate rows per block
#define BMAX 12        // padded per-block batch (6 pairs)
#define KSPLIT 15      // k-dim split (15*20=300)
#define PROW 13        // padded Part row stride (in floats)
#define HP   302       // padded Hs2 pair stride (in float2)
// smem floats: Hs2[6][HP]f2 + Part[15][60][PROW] + Cs[HS][BMAX]
#define RECUR_SMEM ((6*HP*2 + KSPLIT*NG*PROW + HS*BMAX)*4)

__device__ __forceinline__ int ld_acquire(const int* p){
    int v;
    asm volatile("ld.acquire.gpu.global.s32 %0, [%1];" : "=r"(v) : "l"(p) : "memory");
    return v;
}
__device__ __forceinline__ void red_release(int* p){
    asm volatile("red.release.gpu.global.add.s32 [%0], %1;" :: "l"(p), "r"(1) : "memory");
}

__global__ void __launch_bounds__(256,1) k_recur(
        const float* __restrict__ whhf, const float* __restrict__ whhb){
    extern __shared__ float smdyn[];
    float* Hs2f = smdyn;                        // [6][HP] float2 pair-major (as floats)
    float* Part = Hs2f + 6*HP*2;                // [15][60][PROW]
    float* Cs   = Part + KSPLIT*NG*PROW;        // [HS][BMAX]

    int bx  = blockIdx.x;
    int dir = bx / (NHS*NBS);
    int r   = bx % (NHS*NBS);
    int hs  = r / NBS;
    int bs  = r % NBS;
    int bch = (bs<2)?11:10;
    int b0g = bs*11;
    int j0  = hs*HS;
    const float* whh = dir ? whhb : whhf;
    int t = threadIdx.x;

    // gemm mapping: half-warp groups share kp (h broadcast), gt varies
    bool comp = (t<240) && ((t&15)<15);
    int kp = t>>4;       // 0..14
    int gt = t&15;       // 0..14 (active)

    // W_hh slice in registers: rows gt*4..gt*4+3 (local), k = kp*20..kp*20+19
    float Wreg[4][20];
    if (comp){
        #pragma unroll
        for (int rr=0;rr<4;rr++){
            int lr = gt*4+rr;
            int type = lr/HS, jj = lr - type*HS;
            const float* src = whh + (size_t)(type*HIDD + j0 + jj)*HIDD + kp*20;
            #pragma unroll
            for (int q=0;q<5;q++){
                float4 v = *(const float4*)(src + q*4);
                Wreg[rr][q*4+0]=v.x; Wreg[rr][q*4+1]=v.y;
                Wreg[rr][q*4+2]=v.z; Wreg[rr][q*4+3]=v.w;
            }
        }
    }
    for (int i=t;i<6*HP*2;i+=256) Hs2f[i]=0.f;
    for (int i=t;i<HS*BMAX;i+=256) Cs[i]=0.f;
    __syncthreads();

    int* ctr = g_ctr + dir*NBS + bs;
    bool mycell = (t < HS*bch);
    int cb = t/HS, cj = t - cb*HS;

    for (int step=0; step<Sx; step++){
        int s = dir ? (Sx-1-step) : step;

        // prefetch gx (independent of h; hides DRAM latency under spin)
        float pgi=0.f,pgf=0.f,pgg=0.f,pgo=0.f;
        if (mycell){
            const float* gp = g_gx + ((size_t)(s*Bx + b0g + cb))*NCOL + dir*GATES + (j0+cj);
            pgi=gp[0]; pgf=gp[HIDD]; pgg=gp[2*HIDD]; pgo=gp[3*HIDD];
        }

        if (step>0){
            int sprev = dir ? s+1 : s-1;
            int target = NHS*step;
            while (ld_acquire(ctr) < target) { }
            // vectorized load h(s-1), transpose into pair-major Hs2
            const float* hbase = g_H + (size_t)sprev*Bx*(2*HIDD) + dir*HIDD;
            int n4 = bch*75;
            for (int i=t;i<n4;i+=256){
                int b=i/75, q=i-b*75;
                float4 h = *(const float4*)(hbase + (size_t)(b0g+b)*(2*HIDD) + q*4);
                float* dst = Hs2f + (b>>1)*(HP*2) + (q*4)*2 + (b&1);
                dst[0]=h.x; dst[2]=h.y; dst[4]=h.z; dst[6]=h.w;
            }
        }
        __syncthreads();                                   // A

        // ---- packed-fp32 recurrent GEMM: 4 rows x 6 pairs x 20 k per thread
        if (comp){
            unsigned long long acc[4][6];
            #pragma unroll
            for (int i=0;i<4;i++)
                #pragma unroll
                for (int p=0;p<6;p++) acc[i][p]=pk2(0.f,0.f);
            const float* hb = Hs2f + kp*40;
            #pragma unroll
            for (int c=0;c<5;c++){
                int k=c*4;
                unsigned long long wd[4][4];
                #pragma unroll
                for (int rr=0;rr<4;rr++)
                    #pragma unroll
                    for (int kk=0;kk<4;kk++)
                        wd[rr][kk]=pk2(Wreg[rr][k+kk],Wreg[rr][k+kk]);
                #pragma unroll
                for (int p=0;p<6;p++){
                    const float* ha = hb + p*(HP*2) + k*2;
                    ulonglong2 h01 = *(const ulonglong2*)(ha);
                    ulonglong2 h23 = *(const ulonglong2*)(ha+4);
                    #pragma unroll
                    for (int rr=0;rr<4;rr++){
                        ffma2(acc[rr][p], wd[rr][0], h01.x);
                        ffma2(acc[rr][p], wd[rr][1], h01.y);
                        ffma2(acc[rr][p], wd[rr][2], h23.x);
                        ffma2(acc[rr][p], wd[rr][3], h23.y);
                    }
                }
            }
            #pragma unroll
            for (int rr=0;rr<4;rr++){
                int row = gt*4+rr;
                #pragma unroll
                for (int p=0;p<6;p++){
                    float lo,hi; upk2(lo,hi,acc[rr][p]);
                    Part[(kp*NG+row)*PROW + 2*p  ]=lo;
                    Part[(kp*NG+row)*PROW + 2*p+1]=hi;
                }
            }
        }
        __syncthreads();                                   // B

        // ---- cell update
        if (mycell){
            float gi=pgi, gf=pgf, gg=pgg, go=pgo;
            #pragma unroll
            for (int kq=0;kq<KSPLIT;kq++){
                gi += Part[(kq*NG + 0*HS+cj)*PROW + cb];
                gf += Part[(kq*NG + 1*HS+cj)*PROW + cb];
                gg += Part[(kq*NG + 2*HS+cj)*PROW + cb];
                go += Part[(kq*NG + 3*HS+cj)*PROW + cb];
            }
            float co=Cs[cj*BMAX+cb];
            float cn=fsigm(gf)*co + fsigm(gi)*ftanh(gg);
            float hn=fsigm(go)*ftanh(cn);
            Cs[cj*BMAX+cb]=cn;
            g_H[((size_t)(s*Bx + b0g + cb))*(2*HIDD) + dir*HIDD + j0 + cj]=hn;
        }
        __syncthreads();                                   // C
        if (t==0) red_release(ctr);
    }
}

// ---------------- K3a: logits + softmax + CRF numerator terms ----------------
__global__ void __launch_bounds__(288) k_head(
        const float* __restrict__ linw, const float* __restrict__ linb,
        const int* __restrict__ y, const float* __restrict__ start_t,
        const float* __restrict__ end_t, const float* __restrict__ trans,
        float* __restrict__ out){
    __shared__ float sh[2*HIDD];
    __shared__ float lg[NTAG];
    int bxid=blockIdx.x;
    int b=bxid/Sx, s=bxid%Sx;
    int t=threadIdx.x;
    const float* hrow=g_H + (size_t)(s*Bx+b)*(2*HIDD);
    for (int k=t;k<2*HIDD;k+=288) sh[k]=hrow[k];
    __syncthreads();
    int w=t>>5, lane=t&31;
    float acc=0.f;
    for (int k=lane;k<2*HIDD;k+=32) acc=fmaf(sh[k],__ldg(&linw[w*(2*HIDD)+k]),acc);
    #pragma unroll
    for (int off=16;off;off>>=1) acc += __shfl_down_sync(0xffffffffu,acc,off);
    if (lane==0) lg[w]=acc+__ldg(&linb[w]);
    __syncthreads();
    if (t==0){
        float m=lg[0];
        #pragma unroll
        for (int i=1;i<NTAG;i++) m=fmaxf(m,lg[i]);
        float e[NTAG]; float ssum=0.f;
        #pragma unroll
        for (int i=0;i<NTAG;i++){ e[i]=expf(lg[i]-m); ssum+=e[i]; }
        float inv=1.f/ssum;
        float* po=out + ((size_t)b*Sx + s)*NTAG;
        float pr[NTAG];
        #pragma unroll
        for (int i=0;i<NTAG;i++){ pr[i]=e[i]*inv; po[i]=pr[i]; }
        int yc=__ldg(&y[b*Sx+s]);
        float term=pr[yc];
        if (s==0) term += __ldg(&start_t[yc]);
        else      term += __ldg(&trans[__ldg(&y[b*Sx+s-1])*NTAG + yc]);
        if (s==Sx-1) term += __ldg(&end_t[yc]);
        g_sc[b*Sx+s]=term;
    }
}

// ---------------- K3b: CRF forward, warp-per-batch (no block syncs in loop) ----
__global__ void __launch_bounds__(1024) k_crf(
        const float* __restrict__ start_t, const float* __restrict__ end_t,
        const float* __restrict__ trans, float* __restrict__ out){
    __shared__ float res[Bx];
    const float* probs = out;    // written by k_head
    int t=threadIdx.x;
    int w=t>>5, lane=t&31;       // warp w = batch w
    int j = (lane<NTAG)? lane : 0;

    float tcol[NTAG];
    #pragma unroll
    for (int i=0;i<NTAG;i++) tcol[i]=__ldg(&trans[i*NTAG+j]);

    float alpha = __ldg(&start_t[j]) + probs[((size_t)w*Sx+0)*NTAG+j];
    float em_next = probs[((size_t)w*Sx+1)*NTAG+j];
    for (int s=1;s<Sx;s++){
        float em = em_next;
        if (s<Sx-1) em_next = probs[((size_t)w*Sx+s+1)*NTAG+j];
        float a[NTAG];
        #pragma unroll
        for (int i=0;i<NTAG;i++) a[i]=__shfl_sync(0xffffffffu, alpha, i);
        float m=-1e30f;
        #pragma unroll
        for (int i=0;i<NTAG;i++){ a[i]+=tcol[i]; m=fmaxf(m,a[i]); }
        float ssum=0.f;
        #pragma unroll
        for (int i=0;i<NTAG;i++) ssum+=__expf(a[i]-m);
        alpha = m + __logf(ssum) + em;
    }
    float v = alpha + __ldg(&end_t[j]);
    float vm=-1e30f;
    #pragma unroll
    for (int i=0;i<NTAG;i++) vm=fmaxf(vm,__shfl_sync(0xffffffffu,v,i));
    float se=0.f;
    #pragma unroll
    for (int i=0;i<NTAG;i++) se+=__expf(__shfl_sync(0xffffffffu,v,i)-vm);
    float denom = vm + __logf(se);
    float sc=0.f;
    for (int s=lane;s<Sx;s+=32) sc+=g_sc[w*Sx+s];
    #pragma unroll
    for (int off=16;off;off>>=1) sc += __shfl_down_sync(0xffffffffu,sc,off);
    if (lane==0) res[w]=sc-denom;
    __syncthreads();
    if (t==0){
        float llh=0.f;
        #pragma unroll
        for (int bb=0;bb<Bx;bb++) llh+=res[bb];
        out[(size_t)Bx*Sx*NTAG]=-llh;
    }
}

// ---------------- launcher ----------------
extern "C" void kernel_launch(void* const* d_in, const int* in_sizes, int n_in,
                              void* d_out, int out_size){
    const int*   x     =(const int*)  d_in[0];
    const int*   y     =(const int*)  d_in[1];
    const float* emb   =(const float*)d_in[2];
    const float* wihf  =(const float*)d_in[3];
    const float* whhf  =(const float*)d_in[4];
    const float* bihf  =(const float*)d_in[5];
    const float* bhhf  =(const float*)d_in[6];
    const float* wihb  =(const float*)d_in[7];
    const float* whhb  =(const float*)d_in[8];
    const float* bihb  =(const float*)d_in[9];
    const float* bhhb  =(const float*)d_in[10];
    const float* linw  =(const float*)d_in[11];
    const float* linb  =(const float*)d_in[12];
    const float* startt=(const float*)d_in[13];
    const float* endt  =(const float*)d_in[14];
    const float* trans =(const float*)d_in[15];
    float* out=(float*)d_out;
    (void)in_sizes; (void)n_in; (void)out_size;

    static int smem_set = 0;
    if (!smem_set){
        cudaFuncSetAttribute(k_recur, cudaFuncAttributeMaxDynamicSharedMemorySize, RECUR_SMEM);
        smem_set = 1;
    }

    k_init<<<1,32>>>();
    dim3 gg(8192/128, (NCOL+127)/128);
    k_gx<<<gg,256>>>(x, emb, wihf, wihb, bihf, bhhf, bihb, bhhb);
    k_recur<<<2*NHS*NBS,256,RECUR_SMEM>>>(whhf, whhb);
    k_head<<<Bx*Sx,288>>>(linw, linb, y, startt, endt, trans, out);
    k_crf<<<1,1024>>>(startt, endt, trans, out);
}

// round 7
// speedup vs baseline: 1.8773x; 1.1354x over previous
#include <cuda_runtime.h>
#include <math.h>
#include <stdint.h>

#define Bx   32
#define Sx   256
#define EMBD 300
#define HIDD 300
#define NTAG 9
#define GATES 1200          // 4*HIDD
#define NCOL  2400          // both directions

// ---------------- scratch (static device globals; no allocs) ----------------
__device__ float g_gx[19660800];              // (S,B,2400) input-transform + biases
__device__ float g_H [4915200];               // (S,B,600) hidden states (fwd|bwd)
__device__ float g_sc[Bx*Sx];                 // CRF numerator terms

__device__ __forceinline__ float fsigm(float x){ return 1.f/(1.f+__expf(-x)); }
__device__ __forceinline__ float ftanh(float x){
    float ax=fabsf(x);
    float t=__expf(-2.f*ax);
    float r=(1.f-t)/(1.f+t);
    return copysignf(r,x);
}

// ---- packed fp32x2 helpers (sm_103a FFMA2 path) ----
__device__ __forceinline__ unsigned long long pk2(float lo, float hi){
    unsigned long long r;
    asm("mov.b64 %0, {%1,%2};" : "=l"(r) : "f"(lo), "f"(hi));
    return r;
}
__device__ __forceinline__ void ffma2(unsigned long long& d,
                                      unsigned long long a, unsigned long long b){
    asm("fma.rn.f32x2 %0, %1, %2, %0;" : "+l"(d) : "l"(a), "l"(b));
}
__device__ __forceinline__ void upk2(float& lo, float& hi, unsigned long long v){
    asm("mov.b64 {%0,%1}, %2;" : "=f"(lo), "=f"(hi) : "l"(v));
}

__device__ __forceinline__ uint32_t smem_u32(const void* p){
    uint32_t a;
    asm("{ .reg .u64 t; cvta.to.shared.u64 t, %1; cvt.u32.u64 %0, t; }"
        : "=r"(a) : "l"(p));
    return a;
}
__device__ __forceinline__ float4 dsmem_ld4(uint32_t local_addr, uint32_t rank){
    uint32_t ra; float4 v;
    asm volatile("mapa.shared::cluster.u32 %0, %1, %2;" : "=r"(ra) : "r"(local_addr), "r"(rank));
    asm volatile("ld.shared::cluster.v4.f32 {%0,%1,%2,%3}, [%4];"
        : "=f"(v.x),"=f"(v.y),"=f"(v.z),"=f"(v.w) : "r"(ra));
    return v;
}

// ---------------- K1: fused embed + gx GEMM (8192 x 2400 x 300) --------------
__global__ void __launch_bounds__(256) k_gx(
        const int* __restrict__ x, const float* __restrict__ emb,
        const float* __restrict__ wf, const float* __restrict__ wb,
        const float* __restrict__ bif, const float* __restrict__ bhf,
        const float* __restrict__ bib, const float* __restrict__ bhb){
    __shared__ float As[8][132];
    __shared__ float Bs[8][128];
    int t  = threadIdx.x;
    int m0 = blockIdx.x*128;
    int n0 = blockIdx.y*128;
    int tx = t & 15, ty = t >> 4;

    unsigned long long acc2[8][4];
    #pragma unroll
    for (int i=0;i<8;i++)
        #pragma unroll
        for (int j=0;j<4;j++) acc2[i][j]=pk2(0.f,0.f);

    int arow = t>>1, ahalf = t&1;
    int bn = t>>1,  bh = t&1;
    int m_ = m0 + arow;
    int s_ = m_ >> 5, b_ = m_ & 31;
    const float* arowp = emb + (size_t)__ldg(&x[b_*Sx + s_])*EMBD;

    bool brow_ok = (n0+bn) < NCOL;
    const float* wrp = brow_ok
        ? ((n0+bn) < GATES ? wf + (size_t)(n0+bn)*EMBD
                           : wb + (size_t)(n0+bn-GATES)*EMBD)
        : wf;

    float4 aR, bRv;
    {
        aR  = *(const float4*)(arowp + ahalf*4);
        bRv = brow_ok ? *(const float4*)(wrp + bh*4)
                      : make_float4(0.f,0.f,0.f,0.f);
    }
    for (int ck=0; ck<38; ck++){
        __syncthreads();
        {   float av[4]={aR.x,aR.y,aR.z,aR.w};
            float bv[4]={bRv.x,bRv.y,bRv.z,bRv.w};
            #pragma unroll
            for (int i=0;i<4;i++){ As[ahalf*4+i][arow]=av[i]; Bs[bh*4+i][bn]=bv[i]; }
        }
        __syncthreads();
        if (ck < 37){
            int k0=(ck+1)*8;
            int ka = k0 + ahalf*4;
            int kb = k0 + bh*4;
            aR = (ka<EMBD) ? *(const float4*)(arowp + ka)
                           : make_float4(0.f,0.f,0.f,0.f);
            bRv = (brow_ok && kb<EMBD) ? *(const float4*)(wrp + kb)
                                       : make_float4(0.f,0.f,0.f,0.f);
        }
        #pragma unroll
        for (int kk=0;kk<8;kk++){
            float4 a0=*(const float4*)&As[kk][ty*8];
            float4 a1=*(const float4*)&As[kk][ty*8+4];
            float av[8]={a0.x,a0.y,a0.z,a0.w,a1.x,a1.y,a1.z,a1.w};
            unsigned long long ad[8];
            #pragma unroll
            for (int i=0;i<8;i++) ad[i]=pk2(av[i],av[i]);
            ulonglong2 bq0 = *(const ulonglong2*)&Bs[kk][tx*8];
            ulonglong2 bq1 = *(const ulonglong2*)&Bs[kk][tx*8+4];
            unsigned long long bp[4]={bq0.x,bq0.y,bq1.x,bq1.y};
            #pragma unroll
            for (int i=0;i<8;i++)
                #pragma unroll
                for (int j=0;j<4;j++)
                    ffma2(acc2[i][j], ad[i], bp[j]);
        }
    }
    #pragma unroll
    for (int i=0;i<8;i++){
        int gm = m0 + ty*8 + i;
        float vv[8];
        #pragma unroll
        for (int j=0;j<4;j++) upk2(vv[2*j], vv[2*j+1], acc2[i][j]);
        #pragma unroll
        for (int j0=0;j0<8;j0+=4){
            int gn = n0 + tx*8 + j0;
            if (gn < NCOL){
                float ww[4];
                #pragma unroll
                for (int j=0;j<4;j++){
                    int c=gn+j;
                    float bias = (c<GATES)? bif[c]+bhf[c] : bib[c-GATES]+bhb[c-GATES];
                    ww[j]=vv[j0+j]+bias;
                }
                *(float4*)(g_gx + (size_t)gm*NCOL + gn) =
                    make_float4(ww[0],ww[1],ww[2],ww[3]);
            }
        }
    }
}

// ---------------- K2: cluster-parallel persistent BiLSTM recurrence ----------
#define HSC   25        // hidden units per CTA
#define NHSC  12        // CTAs per cluster (hidden slices)
#define NBSC  4         // batch slices (8 each)
#define BCH   8         // batch per CTA
#define NGC   100       // 4*HSC gate rows per CTA
#define KSP   12        // k chunks
#define KCH   25        // k per chunk
#define PROWC 9         // padded Part row stride
// smem floats: Hs2[300][8] + Hout[2][200] + Part[12][100][9] + Cs[200]
#define HS2_OFF  0
#define HOUT_OFF 2400
#define PART_OFF 2800
#define CS_OFF   13600
#define RECUR_SMEM ((13800)*4)

__global__ void __launch_bounds__(256,1) k_recur(
        const float* __restrict__ whhf, const float* __restrict__ whhb){
    extern __shared__ float sm[];
    float* Hs2  = sm + HS2_OFF;    // [300][8]  full h(s-1), k-major x batch
    float* Hout = sm + HOUT_OFF;   // [2][25*8] own h slice, double buffered
    float* Part = sm + PART_OFF;   // [12][100][9]
    float* Cs   = sm + CS_OFF;     // [25*8]

    int t = threadIdx.x;
    int cid  = blockIdx.x / NHSC;
    uint32_t rank = blockIdx.x % NHSC;
    int dir = cid >> 2;
    int bs  = cid & 3;
    int b0g = bs*BCH;
    int j0  = rank*HSC;
    const float* whh = dir ? whhb : whhf;

    // compute mapping: 240 threads, kp=t/20 (k chunk of 25), gt=t%20 (5 rows)
    bool comp = (t < 240);
    int kp = t/20, gt = t%20;

    // W_hh slice in registers: rows gt*5..gt*5+4, k = kp*25..kp*25+24
    float W[5][25];
    if (comp){
        #pragma unroll
        for (int rr=0;rr<5;rr++){
            int lr = gt*5+rr;
            int type = lr/HSC, jj = lr - type*HSC;
            const float* src = whh + (size_t)(type*HIDD + j0 + jj)*HIDD + kp*KCH;
            #pragma unroll
            for (int k=0;k<KCH;k++) W[rr][k]=src[k];
        }
    }
    for (int i=t;i<2400;i+=256) Hs2[i]=0.f;
    for (int i=t;i<400;i+=256)  Hout[i]=0.f;
    for (int i=t;i<200;i+=256)  Cs[i]=0.f;
    __syncthreads();

    bool mycell = (t < 200);
    int cb = t/HSC, cj = t - cb*HSC;   // batch, hidden-within-slice
    uint32_t smb = smem_u32(sm);

    for (int step=0; step<Sx; step++){
        int s = dir ? (Sx-1-step) : step;
        int buf = step & 1;

        // prefetch gx (independent of h)
        float pgi=0.f,pgf=0.f,pgg=0.f,pgo=0.f;
        if (mycell){
            const float* gp = g_gx + ((size_t)(s*Bx + b0g + cb))*NCOL + dir*GATES + (j0+cj);
            pgi=gp[0]; pgf=gp[HIDD]; pgg=gp[2*HIDD]; pgo=gp[3*HIDD];
        }

        // gather full h(s-1) from cluster peers' smem (DSMEM)
        if (step>0){
            int pbuf = (step-1)&1;
            for (int i=t;i<600;i+=256){
                int k = i>>1, half = i&1;
                uint32_t peer = (uint32_t)(k/HSC);
                int koff = k - (int)peer*HSC;
                uint32_t la = smb + (uint32_t)((HOUT_OFF + pbuf*200 + koff*8 + half*4)*4);
                float4 v = dsmem_ld4(la, peer);
                ((float4*)Hs2)[i] = v;
            }
        }
        __syncthreads();                                    // A

        // recurrent GEMM: 5 rows x 4 batch-pairs x 25 k per thread (f32x2)
        if (comp){
            unsigned long long acc[5][4];
            #pragma unroll
            for (int rr=0;rr<5;rr++)
                #pragma unroll
                for (int p=0;p<4;p++) acc[rr][p]=pk2(0.f,0.f);
            const float* hbase = Hs2 + (kp*KCH)*8;
            #pragma unroll
            for (int c=0;c<KCH;c++){
                ulonglong2 hA = *(const ulonglong2*)(hbase + c*8);
                ulonglong2 hB = *(const ulonglong2*)(hbase + c*8 + 4);
                unsigned long long hp[4]={hA.x,hA.y,hB.x,hB.y};
                #pragma unroll
                for (int rr=0;rr<5;rr++){
                    unsigned long long wd = pk2(W[rr][c],W[rr][c]);
                    #pragma unroll
                    for (int p=0;p<4;p++) ffma2(acc[rr][p], wd, hp[p]);
                }
            }
            #pragma unroll
            for (int rr=0;rr<5;rr++){
                int row = gt*5+rr;
                #pragma unroll
                for (int p=0;p<4;p++){
                    float lo,hi; upk2(lo,hi,acc[rr][p]);
                    Part[(kp*NGC+row)*PROWC + 2*p  ]=lo;
                    Part[(kp*NGC+row)*PROWC + 2*p+1]=hi;
                }
            }
        }
        __syncthreads();                                    // B

        // cell update
        if (mycell){
            float gi=pgi, gf=pgf, gg=pgg, go=pgo;
            #pragma unroll
            for (int kq=0;kq<KSP;kq++){
                gi += Part[(kq*NGC + 0*HSC+cj)*PROWC + cb];
                gf += Part[(kq*NGC + 1*HSC+cj)*PROWC + cb];
                gg += Part[(kq*NGC + 2*HSC+cj)*PROWC + cb];
                go += Part[(kq*NGC + 3*HSC+cj)*PROWC + cb];
            }
            float co=Cs[cj*8+cb];
            float cn=fsigm(gf)*co + fsigm(gi)*ftanh(gg);
            float hn=fsigm(go)*ftanh(cn);
            Cs[cj*8+cb]=cn;
            Hout[buf*200 + cj*8 + cb]=hn;
            g_H[((size_t)(s*Bx + b0g + cb))*(2*HIDD) + dir*HIDD + j0 + cj]=hn;
        }
        // cluster-wide barrier: orders Hout writes vs peers' next-step gather,
        // and doubles as the intra-CTA barrier for this step's tail.
        asm volatile("barrier.cluster.arrive.aligned;" ::: "memory");
        asm volatile("barrier.cluster.wait.aligned;"   ::: "memory");
    }
}

// ---------------- K3a: logits + softmax + CRF numerator terms ----------------
__global__ void __launch_bounds__(288) k_head(
        const float* __restrict__ linw, const float* __restrict__ linb,
        const int* __restrict__ y, const float* __restrict__ start_t,
        const float* __restrict__ end_t, const float* __restrict__ trans,
        float* __restrict__ out){
    __shared__ float sh[2*HIDD];
    __shared__ float lg[NTAG];
    int bxid=blockIdx.x;
    int b=bxid/Sx, s=bxid%Sx;
    int t=threadIdx.x;
    const float* hrow=g_H + (size_t)(s*Bx+b)*(2*HIDD);
    for (int k=t;k<2*HIDD;k+=288) sh[k]=hrow[k];
    __syncthreads();
    int w=t>>5, lane=t&31;
    float acc=0.f;
    for (int k=lane;k<2*HIDD;k+=32) acc=fmaf(sh[k],__ldg(&linw[w*(2*HIDD)+k]),acc);
    #pragma unroll
    for (int off=16;off;off>>=1) acc += __shfl_down_sync(0xffffffffu,acc,off);
    if (lane==0) lg[w]=acc+__ldg(&linb[w]);
    __syncthreads();
    if (t==0){
        float m=lg[0];
        #pragma unroll
        for (int i=1;i<NTAG;i++) m=fmaxf(m,lg[i]);
        float e[NTAG]; float ssum=0.f;
        #pragma unroll
        for (int i=0;i<NTAG;i++){ e[i]=expf(lg[i]-m); ssum+=e[i]; }
        float inv=1.f/ssum;
        float* po=out + ((size_t)b*Sx + s)*NTAG;
        float pr[NTAG];
        #pragma unroll
        for (int i=0;i<NTAG;i++){ pr[i]=e[i]*inv; po[i]=pr[i]; }
        int yc=__ldg(&y[b*Sx+s]);
        float term=pr[yc];
        if (s==0) term += __ldg(&start_t[yc]);
        else      term += __ldg(&trans[__ldg(&y[b*Sx+s-1])*NTAG + yc]);
        if (s==Sx-1) term += __ldg(&end_t[yc]);
        g_sc[b*Sx+s]=term;
    }
}

// ---------------- K3b: CRF forward, warp-per-batch ----------------
__global__ void __launch_bounds__(1024) k_crf(
        const float* __restrict__ start_t, const float* __restrict__ end_t,
        const float* __restrict__ trans, float* __restrict__ out){
    __shared__ float res[Bx];
    const float* probs = out;    // written by k_head
    int t=threadIdx.x;
    int w=t>>5, lane=t&31;       // warp w = batch w
    int j = (lane<NTAG)? lane : 0;

    float tcol[NTAG];
    #pragma unroll
    for (int i=0;i<NTAG;i++) tcol[i]=__ldg(&trans[i*NTAG+j]);

    float alpha = __ldg(&start_t[j]) + probs[((size_t)w*Sx+0)*NTAG+j];
    float em_next = probs[((size_t)w*Sx+1)*NTAG+j];
    for (int s=1;s<Sx;s++){
        float em = em_next;
        if (s<Sx-1) em_next = probs[((size_t)w*Sx+s+1)*NTAG+j];
        float a[NTAG];
        #pragma unroll
        for (int i=0;i<NTAG;i++) a[i]=__shfl_sync(0xffffffffu, alpha, i);
        float m=-1e30f;
        #pragma unroll
        for (int i=0;i<NTAG;i++){ a[i]+=tcol[i]; m=fmaxf(m,a[i]); }
        float ssum=0.f;
        #pragma unroll
        for (int i=0;i<NTAG;i++) ssum+=__expf(a[i]-m);
        alpha = m + __logf(ssum) + em;
    }
    float v = alpha + __ldg(&end_t[j]);
    float vm=-1e30f;
    #pragma unroll
    for (int i=0;i<NTAG;i++) vm=fmaxf(vm,__shfl_sync(0xffffffffu,v,i));
    float se=0.f;
    #pragma unroll
    for (int i=0;i<NTAG;i++) se+=__expf(__shfl_sync(0xffffffffu,v,i)-vm);
    float denom = vm + __logf(se);
    float sc=0.f;
    for (int s=lane;s<Sx;s+=32) sc+=g_sc[w*Sx+s];
    #pragma unroll
    for (int off=16;off;off>>=1) sc += __shfl_down_sync(0xffffffffu,sc,off);
    if (lane==0) res[w]=sc-denom;
    __syncthreads();
    if (t==0){
        float llh=0.f;
        #pragma unroll
        for (int bb=0;bb<Bx;bb++) llh+=res[bb];
        out[(size_t)Bx*Sx*NTAG]=-llh;
    }
}

// ---------------- launcher ----------------
extern "C" void kernel_launch(void* const* d_in, const int* in_sizes, int n_in,
                              void* d_out, int out_size){
    const int*   x     =(const int*)  d_in[0];
    const int*   y     =(const int*)  d_in[1];
    const float* emb   =(const float*)d_in[2];
    const float* wihf  =(const float*)d_in[3];
    const float* whhf  =(const float*)d_in[4];
    const float* bihf  =(const float*)d_in[5];
    const float* bhhf  =(const float*)d_in[6];
    const float* wihb  =(const float*)d_in[7];
    const float* whhb  =(const float*)d_in[8];
    const float* bihb  =(const float*)d_in[9];
    const float* bhhb  =(const float*)d_in[10];
    const float* linw  =(const float*)d_in[11];
    const float* linb  =(const float*)d_in[12];
    const float* startt=(const float*)d_in[13];
    const float* endt  =(const float*)d_in[14];
    const float* trans =(const float*)d_in[15];
    float* out=(float*)d_out;
    (void)in_sizes; (void)n_in; (void)out_size;

    static int once = 0;
    if (!once){
        cudaFuncSetAttribute(k_recur, cudaFuncAttributeMaxDynamicSharedMemorySize, RECUR_SMEM);
        cudaFuncSetAttribute(k_recur, cudaFuncAttributeNonPortableClusterSizeAllowed, 1);
        once = 1;
    }

    dim3 gg(8192/128, (NCOL+127)/128);
    k_gx<<<gg,256>>>(x, emb, wihf, wihb, bihf, bhhf, bihb, bhhb);

    cudaLaunchConfig_t cfg = {};
    cfg.gridDim = dim3(2*NBSC*NHSC, 1, 1);   // 96 CTAs = 8 clusters x 12
    cfg.blockDim = dim3(256, 1, 1);
    cfg.dynamicSmemBytes = RECUR_SMEM;
    cfg.stream = 0;
    cudaLaunchAttribute attrs[1];
    attrs[0].id = cudaLaunchAttributeClusterDimension;
    attrs[0].val.clusterDim.x = NHSC;
    attrs[0].val.clusterDim.y = 1;
    attrs[0].val.clusterDim.z = 1;
    cfg.attrs = attrs;
    cfg.numAttrs = 1;
    cudaLaunchKernelEx(&cfg, k_recur, whhf, whhb);

    k_head<<<Bx*Sx,288>>>(linw, linb, y, startt, endt, trans, out);
    k_crf<<<1,1024>>>(startt, endt, trans, out);
}

// round 8
// speedup vs baseline: 2.0380x; 1.0856x over previous
#include <cuda_runtime.h>
#include <math.h>
#include <stdint.h>

#define Bx   32
#define Sx   256
#define EMBD 300
#define HIDD 300
#define NTAG 9
#define GATES 1200          // 4*HIDD
#define NCOL  2400          // both directions

// ---------------- scratch (static device globals; no allocs) ----------------
__device__ float g_gx[19660800];              // (S,B,2400) input-transform + biases
__device__ float g_H [4915200];               // (S,B,600) hidden states (fwd|bwd)
__device__ float g_sc[Bx*Sx];                 // CRF numerator terms
__device__ float g_res[Bx];                   // per-batch llh terms

__device__ __forceinline__ float fsigm(float x){ return 1.f/(1.f+__expf(-x)); }
__device__ __forceinline__ float ftanh(float x){
    float ax=fabsf(x);
    float t=__expf(-2.f*ax);
    float r=(1.f-t)/(1.f+t);
    return copysignf(r,x);
}

// ---- packed fp32x2 helpers (sm_103a FFMA2 path) ----
__device__ __forceinline__ unsigned long long pk2(float lo, float hi){
    unsigned long long r;
    asm("mov.b64 %0, {%1,%2};" : "=l"(r) : "f"(lo), "f"(hi));
    return r;
}
__device__ __forceinline__ void ffma2(unsigned long long& d,
                                      unsigned long long a, unsigned long long b){
    asm("fma.rn.f32x2 %0, %1, %2, %0;" : "+l"(d) : "l"(a), "l"(b));
}

__device__ __forceinline__ uint32_t smem_u32(const void* p){
    uint32_t a;
    asm("{ .reg .u64 t; cvta.to.shared.u64 t, %1; cvt.u32.u64 %0, t; }"
        : "=r"(a) : "l"(p));
    return a;
}
__device__ __forceinline__ float4 dsmem_ld4(uint32_t local_addr, uint32_t rank){
    uint32_t ra; float4 v;
    asm volatile("mapa.shared::cluster.u32 %0, %1, %2;" : "=r"(ra) : "r"(local_addr), "r"(rank));
    asm volatile("ld.shared::cluster.v4.f32 {%0,%1,%2,%3}, [%4];"
        : "=f"(v.x),"=f"(v.y),"=f"(v.z),"=f"(v.w) : "r"(ra));
    return v;
}

// ---------------- K1: fused embed + gx GEMM (8192 x 2400 x 300) --------------
__global__ void __launch_bounds__(256) k_gx(
        const int* __restrict__ x, const float* __restrict__ emb,
        const float* __restrict__ wf, const float* __restrict__ wb,
        const float* __restrict__ bif, const float* __restrict__ bhf,
        const float* __restrict__ bib, const float* __restrict__ bhb){
    __shared__ float As[8][132];
    __shared__ float Bs[8][128];
    int t  = threadIdx.x;
    int m0 = blockIdx.x*128;
    int n0 = blockIdx.y*128;
    int tx = t & 15, ty = t >> 4;

    unsigned long long acc2[8][4];
    #pragma unroll
    for (int i=0;i<8;i++)
        #pragma unroll
        for (int j=0;j<4;j++) acc2[i][j]=pk2(0.f,0.f);

    int arow = t>>1, ahalf = t&1;
    int bn = t>>1,  bh = t&1;
    int m_ = m0 + arow;
    int s_ = m_ >> 5, b_ = m_ & 31;
    const float* arowp = emb + (size_t)__ldg(&x[b_*Sx + s_])*EMBD;

    bool brow_ok = (n0+bn) < NCOL;
    const float* wrp = brow_ok
        ? ((n0+bn) < GATES ? wf + (size_t)(n0+bn)*EMBD
                           : wb + (size_t)(n0+bn-GATES)*EMBD)
        : wf;

    float4 aR, bRv;
    {
        aR  = *(const float4*)(arowp + ahalf*4);
        bRv = brow_ok ? *(const float4*)(wrp + bh*4)
                      : make_float4(0.f,0.f,0.f,0.f);
    }
    for (int ck=0; ck<38; ck++){
        __syncthreads();
        {   float av[4]={aR.x,aR.y,aR.z,aR.w};
            float bv[4]={bRv.x,bRv.y,bRv.z,bRv.w};
            #pragma unroll
            for (int i=0;i<4;i++){ As[ahalf*4+i][arow]=av[i]; Bs[bh*4+i][bn]=bv[i]; }
        }
        __syncthreads();
        if (ck < 37){
            int k0=(ck+1)*8;
            int ka = k0 + ahalf*4;
            int kb = k0 + bh*4;
            aR = (ka<EMBD) ? *(const float4*)(arowp + ka)
                           : make_float4(0.f,0.f,0.f,0.f);
            bRv = (brow_ok && kb<EMBD) ? *(const float4*)(wrp + kb)
                                       : make_float4(0.f,0.f,0.f,0.f);
        }
        #pragma unroll
        for (int kk=0;kk<8;kk++){
            float4 a0=*(const float4*)&As[kk][ty*8];
            float4 a1=*(const float4*)&As[kk][ty*8+4];
            float av[8]={a0.x,a0.y,a0.z,a0.w,a1.x,a1.y,a1.z,a1.w};
            unsigned long long ad[8];
            #pragma unroll
            for (int i=0;i<8;i++) ad[i]=pk2(av[i],av[i]);
            ulonglong2 bq0 = *(const ulonglong2*)&Bs[kk][tx*8];
            ulonglong2 bq1 = *(const ulonglong2*)&Bs[kk][tx*8+4];
            unsigned long long bp[4]={bq0.x,bq0.y,bq1.x,bq1.y};
            #pragma unroll
            for (int i=0;i<8;i++)
                #pragma unroll
                for (int j=0;j<4;j++)
                    ffma2(acc2[i][j], ad[i], bp[j]);
        }
    }
    #pragma unroll
    for (int i=0;i<8;i++){
        int gm = m0 + ty*8 + i;
        float vv[8];
        #pragma unroll
        for (int j=0;j<4;j++){
            asm("mov.b64 {%0,%1}, %2;" : "=f"(vv[2*j]), "=f"(vv[2*j+1]) : "l"(acc2[i][j]));
        }
        #pragma unroll
        for (int j0=0;j0<8;j0+=4){
            int gn = n0 + tx*8 + j0;
            if (gn < NCOL){
                float ww[4];
                #pragma unroll
                for (int j=0;j<4;j++){
                    int c=gn+j;
                    float bias = (c<GATES)? bif[c]+bhf[c] : bib[c-GATES]+bhb[c-GATES];
                    ww[j]=vv[j0+j]+bias;
                }
                *(float4*)(g_gx + (size_t)gm*NCOL + gn) =
                    make_float4(ww[0],ww[1],ww[2],ww[3]);
            }
        }
    }
}

// ---------------- K2: cluster-parallel persistent BiLSTM recurrence ----------
#define HSC   25        // hidden units per CTA
#define NHSC  12        // CTAs per cluster (hidden slices)
#define NBSC  4         // batch slices (8 each)
#define BCH   8         // batch per CTA
#define NGC   100       // 4*HSC gate rows per CTA
#define KSP   12        // k chunks
#define KCH   25        // k per chunk
#define PROWC 10        // padded Part row stride (even -> 8B-aligned pair stores)
// smem floats: Hs2[300][8] + Hout[2][200] + Part[12][100][10] + Cs[200]
#define HS2_OFF  0
#define HOUT_OFF 2400
#define PART_OFF 2800
#define CS_OFF   (PART_OFF + KSP*NGC*PROWC)
#define RECUR_SMEM ((CS_OFF + 200)*4)

__global__ void __launch_bounds__(256,1) k_recur(
        const float* __restrict__ whhf, const float* __restrict__ whhb){
    extern __shared__ float sm[];
    float* Hs2  = sm + HS2_OFF;    // [300][8]  full h(s-1), k-major x batch
    float* Hout = sm + HOUT_OFF;   // [2][25*8] own h slice, double buffered
    float* Part = sm + PART_OFF;   // [12][100][10]
    float* Cs   = sm + CS_OFF;     // [25*8]

    int t = threadIdx.x;
    int cid  = blockIdx.x / NHSC;
    uint32_t rank = blockIdx.x % NHSC;
    int dir = cid >> 2;
    int bs  = cid & 3;
    int b0g = bs*BCH;
    int j0  = rank*HSC;
    const float* whh = dir ? whhb : whhf;

    bool comp = (t < 240);
    int kp = t/20, gt = t%20;

    float W[5][25];
    if (comp){
        #pragma unroll
        for (int rr=0;rr<5;rr++){
            int lr = gt*5+rr;
            int type = lr/HSC, jj = lr - type*HSC;
            const float* src = whh + (size_t)(type*HIDD + j0 + jj)*HIDD + kp*KCH;
            #pragma unroll
            for (int k=0;k<KCH;k++) W[rr][k]=src[k];
        }
    }
    for (int i=t;i<2400;i+=256) Hs2[i]=0.f;
    for (int i=t;i<400;i+=256)  Hout[i]=0.f;
    for (int i=t;i<200;i+=256)  Cs[i]=0.f;
    __syncthreads();

    bool mycell = (t < 200);
    int cb = t/HSC, cj = t - cb*HSC;
    uint32_t smb = smem_u32(sm);

    // pre-loop arrive pairs with step-0 wait
    asm volatile("barrier.cluster.arrive.aligned;" ::: "memory");

    for (int step=0; step<Sx; step++){
        int s = dir ? (Sx-1-step) : step;
        int buf = step & 1;

        // prefetch gx (independent of peers -> issued before the cluster wait)
        float pgi=0.f,pgf=0.f,pgg=0.f,pgo=0.f;
        if (mycell){
            const float* gp = g_gx + ((size_t)(s*Bx + b0g + cb))*NCOL + dir*GATES + (j0+cj);
            pgi=gp[0]; pgf=gp[HIDD]; pgg=gp[2*HIDD]; pgo=gp[3*HIDD];
        }

        // wait for peers' arrives from previous step (or pre-loop)
        asm volatile("barrier.cluster.wait.aligned;" ::: "memory");

        // gather full h(s-1) from cluster peers' smem (DSMEM)
        if (step>0){
            int pbuf = (step-1)&1;
            for (int i=t;i<600;i+=256){
                int k = i>>1, half = i&1;
                uint32_t peer = (uint32_t)(k/HSC);
                int koff = k - (int)peer*HSC;
                uint32_t la = smb + (uint32_t)((HOUT_OFF + pbuf*200 + koff*8 + half*4)*4);
                float4 v = dsmem_ld4(la, peer);
                ((float4*)Hs2)[i] = v;
            }
        }
        __syncthreads();                                    // A

        // recurrent GEMM: 5 rows x 4 batch-pairs x 25 k per thread (f32x2)
        if (comp){
            unsigned long long acc[5][4];
            #pragma unroll
            for (int rr=0;rr<5;rr++)
                #pragma unroll
                for (int p=0;p<4;p++) acc[rr][p]=pk2(0.f,0.f);
            const float* hbase = Hs2 + (kp*KCH)*8;
            #pragma unroll
            for (int c=0;c<KCH;c++){
                ulonglong2 hA = *(const ulonglong2*)(hbase + c*8);
                ulonglong2 hB = *(const ulonglong2*)(hbase + c*8 + 4);
                unsigned long long hp[4]={hA.x,hA.y,hB.x,hB.y};
                #pragma unroll
                for (int rr=0;rr<5;rr++){
                    unsigned long long wd = pk2(W[rr][c],W[rr][c]);
                    #pragma unroll
                    for (int p=0;p<4;p++) ffma2(acc[rr][p], wd, hp[p]);
                }
            }
            #pragma unroll
            for (int rr=0;rr<5;rr++){
                int row = gt*5+rr;
                #pragma unroll
                for (int p=0;p<4;p++)
                    *(unsigned long long*)&Part[(kp*NGC+row)*PROWC + 2*p] = acc[rr][p];
            }
        }
        __syncthreads();                                    // B

        // cell update
        if (mycell){
            float gi=pgi, gf=pgf, gg=pgg, go=pgo;
            #pragma unroll
            for (int kq=0;kq<KSP;kq++){
                gi += Part[(kq*NGC + 0*HSC+cj)*PROWC + cb];
                gf += Part[(kq*NGC + 1*HSC+cj)*PROWC + cb];
                gg += Part[(kq*NGC + 2*HSC+cj)*PROWC + cb];
                go += Part[(kq*NGC + 3*HSC+cj)*PROWC + cb];
            }
            float co=Cs[cj*8+cb];
            float cn=fsigm(gf)*co + fsigm(gi)*ftanh(gg);
            float hn=fsigm(go)*ftanh(cn);
            Cs[cj*8+cb]=cn;
            Hout[buf*200 + cj*8 + cb]=hn;
            g_H[((size_t)(s*Bx + b0g + cb))*(2*HIDD) + dir*HIDD + j0 + cj]=hn;
        }
        __syncthreads();                                    // C (Hout ready)
        asm volatile("barrier.cluster.arrive.aligned;" ::: "memory");
    }
}

// ---------------- K3a: logits + softmax + CRF numerator terms ----------------
__global__ void __launch_bounds__(288) k_head(
        const float* __restrict__ linw, const float* __restrict__ linb,
        const int* __restrict__ y, const float* __restrict__ start_t,
        const float* __restrict__ end_t, const float* __restrict__ trans,
        float* __restrict__ out){
    __shared__ float sh[2*HIDD];
    __shared__ float lg[NTAG];
    int bxid=blockIdx.x;
    int b=bxid/Sx, s=bxid%Sx;
    int t=threadIdx.x;
    const float* hrow=g_H + (size_t)(s*Bx+b)*(2*HIDD);
    for (int k=t;k<2*HIDD;k+=288) sh[k]=hrow[k];
    __syncthreads();
    int w=t>>5, lane=t&31;
    float acc=0.f;
    for (int k=lane;k<2*HIDD;k+=32) acc=fmaf(sh[k],__ldg(&linw[w*(2*HIDD)+k]),acc);
    #pragma unroll
    for (int off=16;off;off>>=1) acc += __shfl_down_sync(0xffffffffu,acc,off);
    if (lane==0) lg[w]=acc+__ldg(&linb[w]);
    __syncthreads();
    if (t==0){
        float m=lg[0];
        #pragma unroll
        for (int i=1;i<NTAG;i++) m=fmaxf(m,lg[i]);
        float e[NTAG]; float ssum=0.f;
        #pragma unroll
        for (int i=0;i<NTAG;i++){ e[i]=expf(lg[i]-m); ssum+=e[i]; }
        float inv=1.f/ssum;
        float* po=out + ((size_t)b*Sx + s)*NTAG;
        float pr[NTAG];
        #pragma unroll
        for (int i=0;i<NTAG;i++){ pr[i]=e[i]*inv; po[i]=pr[i]; }
        int yc=__ldg(&y[b*Sx+s]);
        float term=pr[yc];
        if (s==0) term += __ldg(&start_t[yc]);
        else      term += __ldg(&trans[__ldg(&y[b*Sx+s-1])*NTAG + yc]);
        if (s==Sx-1) term += __ldg(&end_t[yc]);
        g_sc[b*Sx+s]=term;
    }
}

// ---------------- K3b: CRF forward, one block per batch ----------------
__global__ void __launch_bounds__(32) k_crf(
        const float* __restrict__ start_t, const float* __restrict__ end_t,
        const float* __restrict__ trans, const float* __restrict__ out){
    const float* probs = out;    // written by k_head
    int w = blockIdx.x;          // batch
    int lane = threadIdx.x;
    int j = (lane<NTAG)? lane : 0;

    float tcol[NTAG];
    #pragma unroll
    for (int i=0;i<NTAG;i++) tcol[i]=__ldg(&trans[i*NTAG+j]);

    float alpha = __ldg(&start_t[j]) + probs[((size_t)w*Sx+0)*NTAG+j];
    float em_next = probs[((size_t)w*Sx+1)*NTAG+j];
    for (int s=1;s<Sx;s++){
        float em = em_next;
        if (s<Sx-1) em_next = probs[((size_t)w*Sx+s+1)*NTAG+j];
        float a[NTAG];
        #pragma unroll
        for (int i=0;i<NTAG;i++) a[i]=__shfl_sync(0xffffffffu, alpha, i);
        float m=-1e30f;
        #pragma unroll
        for (int i=0;i<NTAG;i++){ a[i]+=tcol[i]; m=fmaxf(m,a[i]); }
        float ssum=0.f;
        #pragma unroll
        for (int i=0;i<NTAG;i++) ssum+=__expf(a[i]-m);
        alpha = m + __logf(ssum) + em;
    }
    float v = alpha + __ldg(&end_t[j]);
    float vm=-1e30f;
    #pragma unroll
    for (int i=0;i<NTAG;i++) vm=fmaxf(vm,__shfl_sync(0xffffffffu,v,i));
    float se=0.f;
    #pragma unroll
    for (int i=0;i<NTAG;i++) se+=__expf(__shfl_sync(0xffffffffu,v,i)-vm);
    float denom = vm + __logf(se);
    float sc=0.f;
    for (int s=lane;s<Sx;s+=32) sc+=g_sc[w*Sx+s];
    #pragma unroll
    for (int off=16;off;off>>=1) sc += __shfl_down_sync(0xffffffffu,sc,off);
    if (lane==0) g_res[w]=sc-denom;
}

// ---------------- K3c: final deterministic loss sum ----------------
__global__ void __launch_bounds__(32) k_loss(float* __restrict__ out){
    if (threadIdx.x==0){
        float llh=0.f;
        #pragma unroll
        for (int bb=0;bb<Bx;bb++) llh+=g_res[bb];
        out[(size_t)Bx*Sx*NTAG]=-llh;
    }
}

// ---------------- launcher ----------------
extern "C" void kernel_launch(void* const* d_in, const int* in_sizes, int n_in,
                              void* d_out, int out_size){
    const int*   x     =(const int*)  d_in[0];
    const int*   y     =(const int*)  d_in[1];
    const float* emb   =(const float*)d_in[2];
    const float* wihf  =(const float*)d_in[3];
    const float* whhf  =(const float*)d_in[4];
    const float* bihf  =(const float*)d_in[5];
    const float* bhhf  =(const float*)d_in[6];
    const float* wihb  =(const float*)d_in[7];
    const float* whhb  =(const float*)d_in[8];
    const float* bihb  =(const float*)d_in[9];
    const float* bhhb  =(const float*)d_in[10];
    const float* linw  =(const float*)d_in[11];
    const float* linb  =(const float*)d_in[12];
    const float* startt=(const float*)d_in[13];
    const float* endt  =(const float*)d_in[14];
    const float* trans =(const float*)d_in[15];
    float* out=(float*)d_out;
    (void)in_sizes; (void)n_in; (void)out_size;

    static int once = 0;
    if (!once){
        cudaFuncSetAttribute(k_recur, cudaFuncAttributeMaxDynamicSharedMemorySize, RECUR_SMEM);
        cudaFuncSetAttribute(k_recur, cudaFuncAttributeNonPortableClusterSizeAllowed, 1);
        once = 1;
    }

    dim3 gg(8192/128, (NCOL+127)/128);
    k_gx<<<gg,256>>>(x, emb, wihf, wihb, bihf, bhhf, bihb, bhhb);

    cudaLaunchConfig_t cfg = {};
    cfg.gridDim = dim3(2*NBSC*NHSC, 1, 1);   // 96 CTAs = 8 clusters x 12
    cfg.blockDim = dim3(256, 1, 1);
    cfg.dynamicSmemBytes = RECUR_SMEM;
    cfg.stream = 0;
    cudaLaunchAttribute attrs[1];
    attrs[0].id = cudaLaunchAttributeClusterDimension;
    attrs[0].val.clusterDim.x = NHSC;
    attrs[0].val.clusterDim.y = 1;
    attrs[0].val.clusterDim.z = 1;
    cfg.attrs = attrs;
    cfg.numAttrs = 1;
    cudaLaunchKernelEx(&cfg, k_recur, whhf, whhb);

    k_head<<<Bx*Sx,288>>>(linw, linb, y, startt, endt, trans, out);
    k_crf<<<Bx,32>>>(startt, endt, trans, out);
    k_loss<<<1,32>>>(out);
}